// round 16
// speedup vs baseline: 6.8608x; 1.0390x over previous
#include <cuda_runtime.h>
#include <cuda_fp16.h>
#include <math.h>
#include <stdint.h>

// Problem dims (fixed by the dataset)
#define B_DIM 1024
#define T_DIM 128
#define L_DIM 16
#define H_DIM 512
#define D_DIM 64
#define G_DIM 2048          // 4*H
#define TB_DIM (T_DIM * B_DIM)
#define GRID_P 256          // persistent recurrence grid (2 CTAs/SM)
#define NGROUP 16           // CTAs per m-group (share one barrier)

// ---------------------------------------------------------------------------
// Scratch. Activations single fp16; Wih/W2/W3/P3 2-term, Whh/P1/P2 1-term.
// ZW stored fp16 (gate pre-activations, O(1) scale).
// ---------------------------------------------------------------------------
__device__ float    g_bperm[G_DIM];
__device__ float    g_zbias[H_DIM];
__device__ unsigned short g_x1h[B_DIM * H_DIM];
__device__ unsigned short g_x2h[B_DIM * H_DIM];
__device__ unsigned short g_conds_h[B_DIM * H_DIM];
__device__ unsigned short g_W2_h[H_DIM * H_DIM];
__device__ unsigned short g_W2_l[H_DIM * H_DIM];
__device__ unsigned short g_W3_h[H_DIM * H_DIM];
__device__ unsigned short g_W3_l[H_DIM * H_DIM];
__device__ unsigned short g_Wih_h[G_DIM * H_DIM];
__device__ unsigned short g_Wih_l[G_DIM * H_DIM];
__device__ unsigned short g_Whh_h[G_DIM * H_DIM];
__device__ unsigned short g_P1_h[H_DIM * H_DIM];
__device__ unsigned short g_P2_h[H_DIM * H_DIM];
__device__ unsigned short g_P3_h[D_DIM * H_DIM];
__device__ unsigned short g_P3_l[D_DIM * H_DIM];
__device__ float    g_CWB[B_DIM * G_DIM];
__device__ unsigned short g_z_h[(size_t)TB_DIM * H_DIM];   // 128 MB
__device__ unsigned short g_ZW[(size_t)TB_DIM * G_DIM];    // 512 MB (fp16)
__device__ unsigned short g_H_h[(size_t)TB_DIM * H_DIM];
__device__ unsigned short g_y1_h[(size_t)TB_DIM * H_DIM];
__device__ unsigned short g_y2_h[(size_t)TB_DIM * H_DIM];

// Per-m-group barrier counters (one 128B line each; monotonic; reset at end)
__device__ unsigned g_bar_ctrs[16 * 32];
__device__ unsigned g_done_ctr = 0;

// ---------------------------------------------------------------------------
// Helpers
// ---------------------------------------------------------------------------
__device__ __forceinline__ unsigned short h_of(float x) {
    return __half_as_ushort(__float2half_rn(x));
}
__device__ __forceinline__ float f_of(unsigned short u) {
    return __half2float(__ushort_as_half(u));
}
__device__ __forceinline__ void hsplit(float x, unsigned short& hi, unsigned short& lo) {
    __half h = __float2half_rn(x);
    float r = x - __half2float(h);
    __half l = __float2half_rn(r);
    hi = __half_as_ushort(h);
    lo = __half_as_ushort(l);
}

// mma m16n8k16 row.col fp16 -> f32
__device__ __forceinline__ void mma16816(float& c0, float& c1, float& c2, float& c3,
                                         unsigned a0, unsigned a1, unsigned a2, unsigned a3,
                                         unsigned b0, unsigned b1) {
    asm volatile(
        "mma.sync.aligned.m16n8k16.row.col.f32.f16.f16.f32 "
        "{%0,%1,%2,%3}, {%4,%5,%6,%7}, {%8,%9}, {%0,%1,%2,%3};\n"
        : "+f"(c0), "+f"(c1), "+f"(c2), "+f"(c3)
        : "r"(a0), "r"(a1), "r"(a2), "r"(a3), "r"(b0), "r"(b1));
}

__device__ __forceinline__ void ldsm4(unsigned& r0, unsigned& r1,
                                      unsigned& r2, unsigned& r3, uint32_t a) {
    asm volatile("ldmatrix.sync.aligned.m8n8.x4.shared.b16 {%0,%1,%2,%3}, [%4];"
                 : "=r"(r0), "=r"(r1), "=r"(r2), "=r"(r3) : "r"(a));
}

__device__ __forceinline__ void cp_async16(void* sptr, const void* gptr) {
    unsigned sa = (unsigned)__cvta_generic_to_shared(sptr);
    asm volatile("cp.async.cg.shared.global [%0], [%1], 16;\n" :: "r"(sa), "l"(gptr));
}
__device__ __forceinline__ void cp_commit() {
    asm volatile("cp.async.commit_group;\n");
}
template<int N>
__device__ __forceinline__ void cp_wait() {
    asm volatile("cp.async.wait_group %0;\n" :: "n"(N));
}

// ---------------------------------------------------------------------------
// fp16 GEMM: D[M,N] = A@B^T, A single fp16, B = Bh (+ Bl if TERMS==2).
// BK=32 2-stage cp.async, ldmatrix fragments, STR=40 ushorts (conflict-free).
// EPI: 0 = fp32 + bias (CWB)
//      1 = fp16 out: acc + addvec[row % B][col]  (ZW build, CWB fold)
//      2 = fp16 out + bias (+relu if ACT)    (label MLP L2/L3, P1, P2)
//      3 = fp32 + bias, [T,B]->[B,T] perm    (P3)
// ---------------------------------------------------------------------------
template<int BM, int BN, int WM, int WN, int EPI, int ACT, int TERMS>
__global__ void __launch_bounds__((BM / WM) * (BN / WN) * 32, 2)
hgemm(const unsigned short* __restrict__ A,
      const unsigned short* __restrict__ Bh, const unsigned short* __restrict__ Bl,
      const float* __restrict__ bias,
      const float* __restrict__ addvec,
      float* __restrict__ outf,
      unsigned short* __restrict__ outh,
      int M, int N, int K)
{
    constexpr int BK = 32;
    constexpr int STR = BK + 8;              // 40 ushorts
    constexpr int ATI = BM * STR;
    constexpr int BTI = BN * STR;
    constexpr int STAGE = ATI + TERMS * BTI;
    constexpr int WARPS_N = BN / WN;
    constexpr int NTH = (BM / WM) * (BN / WN) * 32;
    constexpr int MI = WM / 16, NI = WN / 8;

    extern __shared__ unsigned short sm[];

    const int tid  = threadIdx.x;
    const int warp = tid >> 5, lane = tid & 31;
    const int g = lane >> 2, t = lane & 3;
    const int wm0 = (warp / WARPS_N) * WM;
    const int wn0 = (warp % WARPS_N) * WN;
    const int m0 = blockIdx.y * BM;
    const int n0 = blockIdx.x * BN;

    const uint32_t smb = (uint32_t)__cvta_generic_to_shared(sm);
    const int aRow = (lane & 7) + ((lane >> 3) & 1) * 8;
    const int aKh  = (lane >> 4) * 16;
    const int bRow = (lane & 7) + (lane >> 4) * 8;
    const int bKh  = ((lane >> 3) & 1) * 16;
    const uint32_t aBase = smb + (uint32_t)(wm0 + aRow) * STR * 2 + aKh;
    const uint32_t bBase = smb + (uint32_t)(ATI + (wn0 + bRow) * STR) * 2 + bKh;

    float acc[MI][NI][4];
#pragma unroll
    for (int mi = 0; mi < MI; mi++)
#pragma unroll
        for (int ni = 0; ni < NI; ni++)
#pragma unroll
            for (int q = 0; q < 4; q++) acc[mi][ni][q] = 0.f;

    auto load_stage = [&](int k0, int s) {
        unsigned short* st = sm + s * STAGE;
#pragma unroll
        for (int i = tid; i < BM * 4; i += NTH) {
            int r = i >> 2, c = i & 3;
            cp_async16(st + r * STR + c * 8, A + (size_t)(m0 + r) * K + k0 + c * 8);
        }
#pragma unroll
        for (int i = tid; i < BN * 4; i += NTH) {
            int r = i >> 2, c = i & 3;
            const size_t gs = (size_t)(n0 + r) * K + k0 + c * 8;
            cp_async16(st + ATI + r * STR + c * 8, Bh + gs);
            if (TERMS == 2)
                cp_async16(st + ATI + BTI + r * STR + c * 8, Bl + gs);
        }
        cp_commit();
    };

    const int KT = K / BK;
    load_stage(0, 0);

    for (int kt = 0; kt < KT; kt++) {
        const int s = kt & 1;
        if (kt + 1 < KT) { load_stage((kt + 1) * BK, s ^ 1); cp_wait<1>(); }
        else             { cp_wait<0>(); }
        __syncthreads();

        const uint32_t stOff = (uint32_t)(s * STAGE) * 2;
        const uint32_t aA = aBase + stOff;
        const uint32_t bH = bBase + stOff;
        const uint32_t bL = bH + (uint32_t)BTI * 2;

#pragma unroll
        for (int kk = 0; kk < BK; kk += 16) {
            unsigned ah[MI][4], bh[NI][2], bl[NI][2];
#pragma unroll
            for (int mi = 0; mi < MI; mi++)
                ldsm4(ah[mi][0], ah[mi][1], ah[mi][2], ah[mi][3],
                      aA + (uint32_t)(mi * 16 * STR + kk) * 2);
#pragma unroll
            for (int p = 0; p < NI / 2; p++) {
                ldsm4(bh[2*p][0], bh[2*p][1], bh[2*p+1][0], bh[2*p+1][1],
                      bH + (uint32_t)(p * 16 * STR + kk) * 2);
                if (TERMS == 2)
                    ldsm4(bl[2*p][0], bl[2*p][1], bl[2*p+1][0], bl[2*p+1][1],
                          bL + (uint32_t)(p * 16 * STR + kk) * 2);
            }
#pragma unroll
            for (int mi = 0; mi < MI; mi++)
#pragma unroll
                for (int ni = 0; ni < NI; ni++) {
                    mma16816(acc[mi][ni][0], acc[mi][ni][1], acc[mi][ni][2], acc[mi][ni][3],
                             ah[mi][0], ah[mi][1], ah[mi][2], ah[mi][3], bh[ni][0], bh[ni][1]);
                    if (TERMS == 2)
                        mma16816(acc[mi][ni][0], acc[mi][ni][1], acc[mi][ni][2], acc[mi][ni][3],
                                 ah[mi][0], ah[mi][1], ah[mi][2], ah[mi][3], bl[ni][0], bl[ni][1]);
                }
        }
        __syncthreads();
    }

    // ---- Epilogues ----
    if (EPI == 0 || EPI == 2 || EPI == 3) {
        float2 bv[NI];
#pragma unroll
        for (int ni = 0; ni < NI; ni++)
            bv[ni] = *(const float2*)(bias + n0 + wn0 + ni * 8 + 2 * t);

#pragma unroll
        for (int mi = 0; mi < MI; mi++) {
            int row0 = m0 + wm0 + mi * 16 + g;
#pragma unroll
            for (int ni = 0; ni < NI; ni++) {
                int col = n0 + wn0 + ni * 8 + 2 * t;
                float v0 = acc[mi][ni][0] + bv[ni].x;
                float v1 = acc[mi][ni][1] + bv[ni].y;
                float v2 = acc[mi][ni][2] + bv[ni].x;
                float v3 = acc[mi][ni][3] + bv[ni].y;
                if (ACT == 1) {
                    v0 = fmaxf(v0, 0.f); v1 = fmaxf(v1, 0.f);
                    v2 = fmaxf(v2, 0.f); v3 = fmaxf(v3, 0.f);
                }
                if (EPI == 0) {
                    *(float2*)(outf + (size_t)row0 * N + col)       = make_float2(v0, v1);
                    *(float2*)(outf + (size_t)(row0 + 8) * N + col) = make_float2(v2, v3);
                } else if (EPI == 2) {
                    *(ushort2*)(outh + (size_t)row0 * N + col) =
                        make_ushort2(h_of(v0), h_of(v1));
                    *(ushort2*)(outh + (size_t)(row0 + 8) * N + col) =
                        make_ushort2(h_of(v2), h_of(v3));
                } else {
                    int tt0 = row0 / B_DIM, bb0 = row0 % B_DIM;
                    int r1 = row0 + 8;
                    int tt1 = r1 / B_DIM, bb1 = r1 % B_DIM;
                    *(float2*)(outf + ((size_t)bb0 * T_DIM + tt0) * D_DIM + col) = make_float2(v0, v1);
                    *(float2*)(outf + ((size_t)bb1 * T_DIM + tt1) * D_DIM + col) = make_float2(v2, v3);
                }
            }
        }
    } else {
        // EPI == 1: fp16 out, + addvec (CWB incl. biases)
#pragma unroll
        for (int mi = 0; mi < MI; mi++) {
            int row0 = m0 + wm0 + mi * 16 + g;
#pragma unroll
            for (int ni = 0; ni < NI; ni++) {
                int col = n0 + wn0 + ni * 8 + 2 * t;
                float2 a0 = *(const float2*)(addvec + (size_t)(row0 & (B_DIM - 1)) * N + col);
                float2 a1 = *(const float2*)(addvec + (size_t)((row0 + 8) & (B_DIM - 1)) * N + col);
                *(ushort2*)(outh + (size_t)row0 * N + col) =
                    make_ushort2(h_of(acc[mi][ni][0] + a0.x), h_of(acc[mi][ni][1] + a0.y));
                *(ushort2*)(outh + (size_t)(row0 + 8) * N + col) =
                    make_ushort2(h_of(acc[mi][ni][2] + a1.x), h_of(acc[mi][ni][3] + a1.y));
            }
        }
    }
}

// ---------------------------------------------------------------------------
// Persistent LSTM recurrence: 256 CTAs (2/SM), tile 64x128, BK=64, Whh 1-term,
// ZW[t] register prefetch. Barrier: PER-M-GROUP (16 CTAs sharing the same
// 64 H-rows sync independently; no global straggler coupling).
// ---------------------------------------------------------------------------
__global__ void __launch_bounds__(256, 2)
lstm_persistent(const unsigned short* __restrict__ Whh_h,
                const unsigned short* __restrict__ ZW,   // fp16 [T][B][G] (perm)
                unsigned short* __restrict__ H_h)
{
    constexpr int BM = 64, BN = 128, BK = 64, WM = 32, WN = 32;
    constexpr int STR = BK + 8;                // 72 ushorts
    constexpr int ATI = BM * STR, BTI = BN * STR;
    constexpr int STAGE = ATI + BTI;
    constexpr int WARPS_N = BN / WN;
    constexpr int NTH = 256;
    constexpr int MI = WM / 16, NI = WN / 8;   // 2, 4
    constexpr int K = H_DIM, N = G_DIM;
    constexpr int KT = K / BK;                 // 8

    extern __shared__ unsigned short sm[];

    const int tid  = threadIdx.x;
    const int warp = tid >> 5, lane = tid & 31;
    const int g = lane >> 2, t4 = lane & 3;
    const int wm0 = (warp / WARPS_N) * WM;
    const int wn0 = (warp % WARPS_N) * WN;
    const int bid = blockIdx.x;
    const int mg = bid >> 4;              // m-group (0..15)
    const int m0 = mg * BM;
    const int n0 = (bid & 15) * BN;

    const uint32_t smb = (uint32_t)__cvta_generic_to_shared(sm);
    const int aRow = (lane & 7) + ((lane >> 3) & 1) * 8;
    const int aKh  = (lane >> 4) * 16;
    const int bRow = (lane & 7) + (lane >> 4) * 8;
    const int bKh  = ((lane >> 3) & 1) * 16;
    const uint32_t aBase = smb + (uint32_t)(wm0 + aRow) * STR * 2 + aKh;
    const uint32_t bBase = smb + (uint32_t)(ATI + (wn0 + bRow) * STR) * 2 + bKh;

    const bool hi_half = (t4 & 1);

    // Per-thread (row, zw-offset) for the cell lanes (fixed across steps)
    int rowIdx[MI];
    size_t zwOff[MI][NI];
#pragma unroll
    for (int mi = 0; mi < MI; mi++) {
        int row0 = m0 + wm0 + mi * 16 + g;
        int row = hi_half ? row0 + 8 : row0;
        rowIdx[mi] = row;
#pragma unroll
        for (int ni = 0; ni < NI; ni++) {
            int col = n0 + wn0 + ni * 8 + 2 * t4;
            zwOff[mi][ni] = (size_t)row * G_DIM + (col & ~3);
        }
    }

    float creg[MI][NI];
#pragma unroll
    for (int mi = 0; mi < MI; mi++)
#pragma unroll
        for (int ni = 0; ni < NI; ni++) creg[mi][ni] = 0.f;

    for (int t = 0; t < T_DIM; t++) {
        // ---- Prefetch ZW[t] into registers (overlaps with MMA below) ----
        const unsigned short* zwb = ZW + (size_t)t * B_DIM * G_DIM;
        ushort4 zpre[MI][NI];
#pragma unroll
        for (int mi = 0; mi < MI; mi++)
#pragma unroll
            for (int ni = 0; ni < NI; ni++)
                zpre[mi][ni] = *(const ushort4*)(zwb + zwOff[mi][ni]);

        float acc[MI][NI][4];
#pragma unroll
        for (int mi = 0; mi < MI; mi++)
#pragma unroll
            for (int ni = 0; ni < NI; ni++)
#pragma unroll
                for (int q = 0; q < 4; q++) acc[mi][ni][q] = 0.f;

        if (t > 0) {
            const unsigned short* Ah = H_h + (size_t)(t - 1) * B_DIM * H_DIM;

            auto load_stage = [&](int k0, int s) {
                unsigned short* st = sm + s * STAGE;
#pragma unroll
                for (int i = tid; i < BM * 8; i += NTH) {
                    int r = i >> 3, c = i & 7;
                    cp_async16(st + r * STR + c * 8, Ah + (size_t)(m0 + r) * K + k0 + c * 8);
                }
#pragma unroll
                for (int i = tid; i < BN * 8; i += NTH) {
                    int r = i >> 3, c = i & 7;
                    cp_async16(st + ATI + r * STR + c * 8,
                               Whh_h + (size_t)(n0 + r) * K + k0 + c * 8);
                }
                cp_commit();
            };

            load_stage(0, 0);
            for (int kt = 0; kt < KT; kt++) {
                const int s = kt & 1;
                if (kt + 1 < KT) { load_stage((kt + 1) * BK, s ^ 1); cp_wait<1>(); }
                else             { cp_wait<0>(); }
                __syncthreads();

                const uint32_t stOff = (uint32_t)(s * STAGE) * 2;
                const uint32_t aA = aBase + stOff;
                const uint32_t bH = bBase + stOff;

#pragma unroll
                for (int kk = 0; kk < BK; kk += 16) {
                    unsigned ah[MI][4], bh[NI][2];
#pragma unroll
                    for (int mi = 0; mi < MI; mi++)
                        ldsm4(ah[mi][0], ah[mi][1], ah[mi][2], ah[mi][3],
                              aA + (uint32_t)(mi * 16 * STR + kk) * 2);
#pragma unroll
                    for (int p = 0; p < NI / 2; p++)
                        ldsm4(bh[2*p][0], bh[2*p][1], bh[2*p+1][0], bh[2*p+1][1],
                              bH + (uint32_t)(p * 16 * STR + kk) * 2);
#pragma unroll
                    for (int mi = 0; mi < MI; mi++)
#pragma unroll
                        for (int ni = 0; ni < NI; ni++)
                            mma16816(acc[mi][ni][0], acc[mi][ni][1], acc[mi][ni][2], acc[mi][ni][3],
                                     ah[mi][0], ah[mi][1], ah[mi][2], ah[mi][3], bh[ni][0], bh[ni][1]);
                }
                __syncthreads();
            }
        }

        // ---- Cell epilogue (c in registers; ZW prefetched) ----
        unsigned short* hh = H_h + (size_t)t * B_DIM * H_DIM;
#pragma unroll
        for (int mi = 0; mi < MI; mi++) {
            int row = rowIdx[mi];
#pragma unroll
            for (int ni = 0; ni < NI; ni++) {
                int col = n0 + wn0 + ni * 8 + 2 * t4;
                float c0 = acc[mi][ni][0], c1 = acc[mi][ni][1];
                float c2 = acc[mi][ni][2], c3 = acc[mi][ni][3];
                float sx = __shfl_xor_sync(0xffffffffu, hi_half ? c0 : c2, 1);
                float sy = __shfl_xor_sync(0xffffffffu, hi_half ? c1 : c3, 1);
                float gi, gf, gg, go;
                if (!hi_half) { gi = c0; gf = c1; gg = sx; go = sy; }
                else          { gi = sx; gf = sy; gg = c2; go = c3; }

                ushort4 zr = zpre[mi][ni];
                gi += f_of(zr.x); gf += f_of(zr.y);
                gg += f_of(zr.z); go += f_of(zr.w);

                float ig = 1.f / (1.f + expf(-gi));
                float fg = 1.f / (1.f + expf(-gf));
                float gt = tanhf(gg);
                float og = 1.f / (1.f + expf(-go));

                float cn = fg * creg[mi][ni] + ig * gt;
                creg[mi][ni] = cn;
                hh[(size_t)row * H_DIM + (col >> 2)] = h_of(og * tanhf(cn));
            }
        }

        // ---- Per-m-group barrier: 16 arrivals, independent per group ----
        if (t < T_DIM - 1) {
            __syncthreads();
            if (tid == 0) {
                __threadfence();
                unsigned* ctr = &g_bar_ctrs[mg * 32];
                atomicAdd(ctr, 1u);
                unsigned target = (unsigned)(t + 1) * NGROUP;
                volatile unsigned* vctr = ctr;
                while (*vctr < target) { }
                __threadfence();
            }
            __syncthreads();
        }
    }

    // Deterministic counter reset for graph replay
    __syncthreads();
    if (tid == 0) {
        unsigned d = atomicAdd(&g_done_ctr, 1u);
        if (d == GRID_P - 1) {
#pragma unroll
            for (int q = 0; q < 16; q++) g_bar_ctrs[q * 32] = 0;
            g_done_ctr = 0;
            __threadfence();
        }
    }
}

// ---------------------------------------------------------------------------
// f32x2 SGEMM (label MLP layer 1, K=16). OUT: 0 fp32, 1 single fp16.
// ---------------------------------------------------------------------------
__device__ __forceinline__ void ffma2(unsigned long long& d,
                                      unsigned long long a,
                                      unsigned long long b) {
    asm("fma.rn.f32x2 %0, %1, %2, %0;" : "+l"(d) : "l"(a), "l"(b));
}
__device__ __forceinline__ unsigned long long pack2(float lo, float hi) {
    unsigned long long r;
    asm("mov.b64 %0, {%1, %2};" : "=l"(r) : "f"(lo), "f"(hi));
    return r;
}
__device__ __forceinline__ float2 unpack2(unsigned long long u) {
    float2 f;
    asm("mov.b64 {%0, %1}, %2;" : "=f"(f.x), "=f"(f.y) : "l"(u));
    return f;
}

template<int BM, int BN, int BK, int TM, int TN, int ACT, int OUT>
__global__ void gemm2_kernel(const float* __restrict__ A,
                             const float* __restrict__ W,
                             const float* __restrict__ bias,
                             float* __restrict__ C,
                             unsigned short* __restrict__ uh,
                             int M, int N, int K)
{
    constexpr int AS_STRIDE = BM + 4;
    constexpr int WS_STRIDE = BN + 4;
    __shared__ float As[BK][AS_STRIDE];
    __shared__ float Ws[BK][WS_STRIDE];

    constexpr int NTH = (BM / TM) * (BN / TN);
    const int tid = threadIdx.x;
    const int tx = tid % (BN / TN);
    const int ty = tid / (BN / TN);
    const int m0 = blockIdx.y * BM;
    const int n0 = blockIdx.x * BN;

    unsigned long long acc2[TM / 2][TN];
#pragma unroll
    for (int p = 0; p < TM / 2; p++)
#pragma unroll
        for (int j = 0; j < TN; j++) acc2[p][j] = 0ULL;

    for (int k0 = 0; k0 < K; k0 += BK) {
#pragma unroll
        for (int i = tid * 4; i < BM * BK; i += NTH * 4) {
            int m = i / BK, k = i % BK;
            float4 v = *(const float4*)(A + (long)(m0 + m) * K + (k0 + k));
            As[k + 0][m] = v.x; As[k + 1][m] = v.y;
            As[k + 2][m] = v.z; As[k + 3][m] = v.w;
        }
#pragma unroll
        for (int i = tid * 4; i < BN * BK; i += NTH * 4) {
            int n = i / BK, k = i % BK;
            float4 v = *(const float4*)(W + (long)(n0 + n) * K + (k0 + k));
            Ws[k + 0][n] = v.x; Ws[k + 1][n] = v.y;
            Ws[k + 2][n] = v.z; Ws[k + 3][n] = v.w;
        }
        __syncthreads();

#pragma unroll
        for (int k = 0; k < BK; k++) {
            unsigned long long am2[TM / 2];
            const ulonglong2* ap = reinterpret_cast<const ulonglong2*>(&As[k][ty * TM]);
#pragma unroll
            for (int q = 0; q < TM / 4; q++) {
                ulonglong2 tt = ap[q];
                am2[2 * q + 0] = tt.x;
                am2[2 * q + 1] = tt.y;
            }
            float4 w4 = *reinterpret_cast<const float4*>(&Ws[k][tx * TN]);
            unsigned long long wd[TN];
            wd[0] = pack2(w4.x, w4.x); wd[1] = pack2(w4.y, w4.y);
            wd[2] = pack2(w4.z, w4.z); wd[3] = pack2(w4.w, w4.w);
#pragma unroll
            for (int p = 0; p < TM / 2; p++)
#pragma unroll
                for (int j = 0; j < TN; j++) ffma2(acc2[p][j], am2[p], wd[j]);
        }
        __syncthreads();
    }

    float4 bv = make_float4(0.f, 0.f, 0.f, 0.f);
    if (bias) bv = *reinterpret_cast<const float4*>(bias + n0 + tx * TN);

#pragma unroll
    for (int p = 0; p < TM / 2; p++) {
        float2 v0 = unpack2(acc2[p][0]);
        float2 v1 = unpack2(acc2[p][1]);
        float2 v2 = unpack2(acc2[p][2]);
        float2 v3 = unpack2(acc2[p][3]);
        float4 rowA = make_float4(v0.x + bv.x, v1.x + bv.y, v2.x + bv.z, v3.x + bv.w);
        float4 rowB = make_float4(v0.y + bv.x, v1.y + bv.y, v2.y + bv.z, v3.y + bv.w);
        if (ACT == 1) {
            rowA.x = fmaxf(rowA.x, 0.f); rowA.y = fmaxf(rowA.y, 0.f);
            rowA.z = fmaxf(rowA.z, 0.f); rowA.w = fmaxf(rowA.w, 0.f);
            rowB.x = fmaxf(rowB.x, 0.f); rowB.y = fmaxf(rowB.y, 0.f);
            rowB.z = fmaxf(rowB.z, 0.f); rowB.w = fmaxf(rowB.w, 0.f);
        }
        int mA = m0 + ty * TM + 2 * p;
        int n  = n0 + tx * TN;
        if (OUT == 0) {
            *reinterpret_cast<float4*>(C + (long)mA * N + n) = rowA;
            *reinterpret_cast<float4*>(C + (long)(mA + 1) * N + n) = rowB;
        } else {
            *(ushort4*)(uh + (size_t)mA * N + n) =
                make_ushort4(h_of(rowA.x), h_of(rowA.y), h_of(rowA.z), h_of(rowA.w));
            *(ushort4*)(uh + (size_t)(mA + 1) * N + n) =
                make_ushort4(h_of(rowB.x), h_of(rowB.y), h_of(rowB.z), h_of(rowB.w));
        }
    }
}

// ---------------------------------------------------------------------------
// Prep kernels
// ---------------------------------------------------------------------------
__device__ __forceinline__ void split4w(const float4* src, int i,
                                        ushort4* hi, ushort4* lo) {
    float4 v = src[i];
    ushort4 h, l;
    hsplit(v.x, h.x, l.x); hsplit(v.y, h.y, l.y);
    hsplit(v.z, h.z, l.z); hsplit(v.w, h.w, l.w);
    hi[i] = h;
    if (lo) lo[i] = l;
}

__device__ __forceinline__ void permsplit4w(const float* src, int i,
                                            ushort4* hi, ushort4* lo) {
    int r = i / (H_DIM / 4);
    int c = i % (H_DIM / 4);
    int j = r >> 2, gg = r & 3;
    float4 v = ((const float4*)src)[(size_t)(gg * H_DIM + j) * (H_DIM / 4) + c];
    ushort4 h, l;
    hsplit(v.x, h.x, l.x); hsplit(v.y, h.y, l.y);
    hsplit(v.z, h.z, l.z); hsplit(v.w, h.w, l.w);
    size_t o = (size_t)r * (H_DIM / 4) + c;
    hi[o] = h;
    if (lo) lo[o] = l;
}

__global__ void prep_weights(const float* __restrict__ P1, const float* __restrict__ P2,
                             const float* __restrict__ P3,
                             const float* __restrict__ Wih, const float* __restrict__ Whh,
                             const float* __restrict__ W2, const float* __restrict__ W3,
                             const float* __restrict__ bih, const float* __restrict__ bhh,
                             ushort4* P1h, ushort4* P2h,
                             ushort4* P3h, ushort4* P3l,
                             ushort4* Wihh, ushort4* Wihl, ushort4* Whhh,
                             ushort4* W2h, ushort4* W2l, ushort4* W3h, ushort4* W3l,
                             float* bp, float* zb)
{
    const int S0 = H_DIM * H_DIM / 4;              // P1
    const int S1 = S0 + H_DIM * H_DIM / 4;         // P2
    const int S2 = S1 + D_DIM * H_DIM / 4;         // P3
    const int S3 = S2 + G_DIM * H_DIM / 4;         // Wih
    const int S4 = S3 + G_DIM * H_DIM / 4;         // Whh
    const int S5 = S4 + H_DIM * H_DIM / 4;         // W2
    const int S6 = S5 + H_DIM * H_DIM / 4;         // W3
    int i = blockIdx.x * blockDim.x + threadIdx.x;
    if      (i < S0) split4w((const float4*)P1, i, P1h, nullptr);
    else if (i < S1) split4w((const float4*)P2, i - S0, P2h, nullptr);
    else if (i < S2) split4w((const float4*)P3, i - S1, P3h, P3l);
    else if (i < S3) permsplit4w(Wih, i - S2, Wihh, Wihl);
    else if (i < S4) permsplit4w(Whh, i - S3, Whhh, nullptr);
    else if (i < S5) split4w((const float4*)W2, i - S4, W2h, W2l);
    else if (i < S6) split4w((const float4*)W3, i - S5, W3h, W3l);
    else if (i < S6 + G_DIM) {
        int k = i - S6;
        int j = k >> 2, gg = k & 3;
        bp[k] = bih[gg * H_DIM + j] + bhh[gg * H_DIM + j];
    }
    else if (i < S6 + G_DIM + H_DIM) {
        zb[i - S6 - G_DIM] = 0.f;
    }
}

// z -> single fp16
__global__ void cvt_half_kernel(const float4* __restrict__ src,
                                ushort4* __restrict__ dst, int n4)
{
    int i = blockIdx.x * blockDim.x + threadIdx.x;
    if (i >= n4) return;
    float4 v = src[i];
    dst[i] = make_ushort4(h_of(v.x), h_of(v.y), h_of(v.z), h_of(v.w));
}

// ---------------------------------------------------------------------------
// Launch
// ---------------------------------------------------------------------------
extern "C" void kernel_launch(void* const* d_in, const int* in_sizes, int n_in,
                              void* d_out, int out_size)
{
    const float* labels = (const float*)d_in[0];
    const float* z      = (const float*)d_in[1];
    const float* W1     = (const float*)d_in[2];
    const float* b1     = (const float*)d_in[3];
    const float* W2     = (const float*)d_in[4];
    const float* b2     = (const float*)d_in[5];
    const float* W3     = (const float*)d_in[6];
    const float* Wih    = (const float*)d_in[7];
    const float* Whh    = (const float*)d_in[8];
    const float* bih    = (const float*)d_in[9];
    const float* bhh    = (const float*)d_in[10];
    const float* P1     = (const float*)d_in[11];
    const float* pb1    = (const float*)d_in[12];
    const float* P2     = (const float*)d_in[13];
    const float* pb2    = (const float*)d_in[14];
    const float* P3     = (const float*)d_in[15];
    const float* pb3    = (const float*)d_in[16];
    float* out = (float*)d_out;

    float *bperm, *zbias, *CWB;
    unsigned short *x1h, *x2h, *conds_h;
    unsigned short *W2_h, *W2_l, *W3_h, *W3_l;
    unsigned short *Wih_h, *Wih_l, *Whh_h;
    unsigned short *P1_h, *P2_h, *P3_h, *P3_l;
    unsigned short *z_h, *ZW, *H_h, *y1_h, *y2_h;
    cudaGetSymbolAddress((void**)&bperm,  g_bperm);
    cudaGetSymbolAddress((void**)&zbias,  g_zbias);
    cudaGetSymbolAddress((void**)&x1h,    g_x1h);
    cudaGetSymbolAddress((void**)&x2h,    g_x2h);
    cudaGetSymbolAddress((void**)&conds_h, g_conds_h);
    cudaGetSymbolAddress((void**)&W2_h,   g_W2_h);
    cudaGetSymbolAddress((void**)&W2_l,   g_W2_l);
    cudaGetSymbolAddress((void**)&W3_h,   g_W3_h);
    cudaGetSymbolAddress((void**)&W3_l,   g_W3_l);
    cudaGetSymbolAddress((void**)&Wih_h,  g_Wih_h);
    cudaGetSymbolAddress((void**)&Wih_l,  g_Wih_l);
    cudaGetSymbolAddress((void**)&Whh_h,  g_Whh_h);
    cudaGetSymbolAddress((void**)&P1_h,   g_P1_h);
    cudaGetSymbolAddress((void**)&P2_h,   g_P2_h);
    cudaGetSymbolAddress((void**)&P3_h,   g_P3_h);
    cudaGetSymbolAddress((void**)&P3_l,   g_P3_l);
    cudaGetSymbolAddress((void**)&CWB,    g_CWB);
    cudaGetSymbolAddress((void**)&z_h,    g_z_h);
    cudaGetSymbolAddress((void**)&ZW,     g_ZW);
    cudaGetSymbolAddress((void**)&H_h,    g_H_h);
    cudaGetSymbolAddress((void**)&y1_h,   g_y1_h);
    cudaGetSymbolAddress((void**)&y2_h,   g_y2_h);

    const int TB = TB_DIM;

    // Dynamic smem: hgemm BK=32 (STR=40); persistent BK=64 (STR=72)
    constexpr int SM128_T2 = 2 * (128 * 40 + 2 * 128 * 40) * 2;  // 61440 B
    constexpr int SM128_T1 = 2 * (128 * 40 + 1 * 128 * 40) * 2;  // 40960 B
    constexpr int SM64_T2  = 2 * (64 * 40 + 2 * 64 * 40) * 2;    // 30720 B (64x64)
    constexpr int SM64B    = 2 * (128 * 40 + 2 * 64 * 40) * 2;   // 40960 B (BN=64)
    constexpr int SMP      = 2 * (64 * 72 + 128 * 72) * 2;       // 55296 B
    cudaFuncSetAttribute((const void*)hgemm<128,128,64,32,0,0,2>,
                         cudaFuncAttributeMaxDynamicSharedMemorySize, SM128_T2);
    cudaFuncSetAttribute((const void*)hgemm<128,128,64,32,1,0,1>,
                         cudaFuncAttributeMaxDynamicSharedMemorySize, SM128_T1);
    cudaFuncSetAttribute((const void*)hgemm<128,128,64,32,2,1,1>,
                         cudaFuncAttributeMaxDynamicSharedMemorySize, SM128_T1);
    cudaFuncSetAttribute((const void*)hgemm<64,64,32,32,2,1,2>,
                         cudaFuncAttributeMaxDynamicSharedMemorySize, SM64_T2);
    cudaFuncSetAttribute((const void*)hgemm<64,64,32,32,2,0,2>,
                         cudaFuncAttributeMaxDynamicSharedMemorySize, SM64_T2);
    cudaFuncSetAttribute((const void*)hgemm<128,64,64,16,3,0,2>,
                         cudaFuncAttributeMaxDynamicSharedMemorySize, SM64B);
    cudaFuncSetAttribute((const void*)lstm_persistent,
                         cudaFuncAttributeMaxDynamicSharedMemorySize, SMP);

    // [0] fused weight prep
    {
        const int total = 4 * (H_DIM * H_DIM / 4) + D_DIM * H_DIM / 4
                        + 2 * (G_DIM * H_DIM / 4) + G_DIM + H_DIM;
        prep_weights<<<(total + 255) / 256, 256>>>(
            P1, P2, P3, Wih, Whh, W2, W3, bih, bhh,
            (ushort4*)P1_h, (ushort4*)P2_h,
            (ushort4*)P3_h, (ushort4*)P3_l,
            (ushort4*)Wih_h, (ushort4*)Wih_l, (ushort4*)Whh_h,
            (ushort4*)W2_h, (ushort4*)W2_l, (ushort4*)W3_h, (ushort4*)W3_l,
            bperm, zbias);
    }
    // [1] z -> fp16
    cvt_half_kernel<<<(int)(((size_t)TB * H_DIM / 4) / 256), 256>>>(
        (const float4*)z, (ushort4*)z_h, TB * (H_DIM / 4));

    // [2] Label MLP layer 1 (K=16, f32x2) -> fp16
    gemm2_kernel<64,64,16,4,4,1,1><<<dim3(H_DIM/64, B_DIM/64), 256>>>(
        labels, W1, b1, nullptr, x1h, B_DIM, H_DIM, L_DIM);
    // [3,4] Label MLP layers 2-3 on tensor cores (64x64 tiles, 128 CTAs)
    hgemm<64,64,32,32,2,1,2><<<dim3(H_DIM/64, B_DIM/64), 128, SM64_T2>>>(
        x1h, W2_h, W2_l, b2, nullptr, nullptr, x2h, B_DIM, H_DIM, H_DIM);
    hgemm<64,64,32,32,2,0,2><<<dim3(H_DIM/64, B_DIM/64), 128, SM64_T2>>>(
        x2h, W3_h, W3_l, zbias, nullptr, nullptr, conds_h, B_DIM, H_DIM, H_DIM);

    // [5] CWB = conds @ Wih_perm^T + (bih+bhh)_perm   (2-term, fp32 out)
    hgemm<128,128,64,32,0,0,2><<<dim3(G_DIM/128, B_DIM/128), 256, SM128_T2>>>(
        conds_h, Wih_h, Wih_l, bperm, nullptr,
        CWB, nullptr, B_DIM, G_DIM, H_DIM);
    // [6] ZW = z @ Wih_perm^T + CWB[row % B]   (1-term, fp16 out)
    hgemm<128,128,64,32,1,0,1><<<dim3(G_DIM/128, TB/128), 256, SM128_T1>>>(
        z_h, Wih_h, nullptr, nullptr, CWB,
        nullptr, ZW, TB, G_DIM, H_DIM);

    // [7] Persistent recurrence (per-m-group barriers)
    lstm_persistent<<<GRID_P, 256, SMP>>>(Whh_h, ZW, H_h);

    // [8..10] Projection MLP over all T*B rows (P1/P2 1-term, P3 2-term)
    hgemm<128,128,64,32,2,1,1><<<dim3(H_DIM/128, TB/128), 256, SM128_T1>>>(
        H_h, P1_h, nullptr, pb1, nullptr,
        nullptr, y1_h, TB, H_DIM, H_DIM);
    hgemm<128,128,64,32,2,1,1><<<dim3(H_DIM/128, TB/128), 256, SM128_T1>>>(
        y1_h, P2_h, nullptr, pb2, nullptr,
        nullptr, y2_h, TB, H_DIM, H_DIM);
    hgemm<128,64,64,16,3,0,2><<<dim3(D_DIM/64, TB/128), 256, SM64B>>>(
        y2_h, P3_h, P3_l, pb3, nullptr,
        out, nullptr, TB, D_DIM, H_DIM);
}

// round 17
// speedup vs baseline: 6.8855x; 1.0036x over previous
#include <cuda_runtime.h>
#include <cuda_fp16.h>
#include <math.h>
#include <stdint.h>

// Problem dims (fixed by the dataset)
#define B_DIM 1024
#define T_DIM 128
#define L_DIM 16
#define H_DIM 512
#define D_DIM 64
#define G_DIM 2048          // 4*H
#define TB_DIM (T_DIM * B_DIM)
#define GRID_P 256          // persistent recurrence grid (2 CTAs/SM)
#define NGROUP 16           // CTAs per m-group (share one barrier)

// ---------------------------------------------------------------------------
// Scratch. Activations single fp16; Wih/W2/W3/P3 2-term, Whh/P1/P2 1-term.
// ZW stored fp16 (gate pre-activations, O(1) scale).
// ---------------------------------------------------------------------------
__device__ float    g_bperm[G_DIM];
__device__ float    g_zbias[H_DIM];
__device__ unsigned short g_x1h[B_DIM * H_DIM];
__device__ unsigned short g_x2h[B_DIM * H_DIM];
__device__ unsigned short g_conds_h[B_DIM * H_DIM];
__device__ unsigned short g_W2_h[H_DIM * H_DIM];
__device__ unsigned short g_W2_l[H_DIM * H_DIM];
__device__ unsigned short g_W3_h[H_DIM * H_DIM];
__device__ unsigned short g_W3_l[H_DIM * H_DIM];
__device__ unsigned short g_Wih_h[G_DIM * H_DIM];
__device__ unsigned short g_Wih_l[G_DIM * H_DIM];
__device__ unsigned short g_Whh_h[G_DIM * H_DIM];
__device__ unsigned short g_P1_h[H_DIM * H_DIM];
__device__ unsigned short g_P2_h[H_DIM * H_DIM];
__device__ unsigned short g_P3_h[D_DIM * H_DIM];
__device__ unsigned short g_P3_l[D_DIM * H_DIM];
__device__ float    g_CWB[B_DIM * G_DIM];
__device__ unsigned short g_z_h[(size_t)TB_DIM * H_DIM];   // 128 MB
__device__ unsigned short g_ZW[(size_t)TB_DIM * G_DIM];    // 512 MB (fp16)
__device__ unsigned short g_H_h[(size_t)TB_DIM * H_DIM];
__device__ unsigned short g_y1_h[(size_t)TB_DIM * H_DIM];
__device__ unsigned short g_y2_h[(size_t)TB_DIM * H_DIM];

// Per-m-group barrier counters (one 128B line each; monotonic; reset at end)
__device__ unsigned g_bar_ctrs[16 * 32];
__device__ unsigned g_done_ctr = 0;

// ---------------------------------------------------------------------------
// Helpers
// ---------------------------------------------------------------------------
__device__ __forceinline__ unsigned short h_of(float x) {
    return __half_as_ushort(__float2half_rn(x));
}
__device__ __forceinline__ float f_of(unsigned short u) {
    return __half2float(__ushort_as_half(u));
}
__device__ __forceinline__ void hsplit(float x, unsigned short& hi, unsigned short& lo) {
    __half h = __float2half_rn(x);
    float r = x - __half2float(h);
    __half l = __float2half_rn(r);
    hi = __half_as_ushort(h);
    lo = __half_as_ushort(l);
}

// Fast activations: force MUFU ex2/rcp path regardless of compiler flags.
// __expf rel err ~2 ulp -> error contribution ~1e-6, negligible vs 6.3e-4.
__device__ __forceinline__ float fsigmoid(float x) {
    return __fdividef(1.f, 1.f + __expf(-x));
}
__device__ __forceinline__ float ftanh(float x) {
    return __fdividef(2.f, 1.f + __expf(-2.f * x)) - 1.f;
}

// mma m16n8k16 row.col fp16 -> f32
__device__ __forceinline__ void mma16816(float& c0, float& c1, float& c2, float& c3,
                                         unsigned a0, unsigned a1, unsigned a2, unsigned a3,
                                         unsigned b0, unsigned b1) {
    asm volatile(
        "mma.sync.aligned.m16n8k16.row.col.f32.f16.f16.f32 "
        "{%0,%1,%2,%3}, {%4,%5,%6,%7}, {%8,%9}, {%0,%1,%2,%3};\n"
        : "+f"(c0), "+f"(c1), "+f"(c2), "+f"(c3)
        : "r"(a0), "r"(a1), "r"(a2), "r"(a3), "r"(b0), "r"(b1));
}

__device__ __forceinline__ void ldsm4(unsigned& r0, unsigned& r1,
                                      unsigned& r2, unsigned& r3, uint32_t a) {
    asm volatile("ldmatrix.sync.aligned.m8n8.x4.shared.b16 {%0,%1,%2,%3}, [%4];"
                 : "=r"(r0), "=r"(r1), "=r"(r2), "=r"(r3) : "r"(a));
}

__device__ __forceinline__ void cp_async16(void* sptr, const void* gptr) {
    unsigned sa = (unsigned)__cvta_generic_to_shared(sptr);
    asm volatile("cp.async.cg.shared.global [%0], [%1], 16;\n" :: "r"(sa), "l"(gptr));
}
__device__ __forceinline__ void cp_commit() {
    asm volatile("cp.async.commit_group;\n");
}
template<int N>
__device__ __forceinline__ void cp_wait() {
    asm volatile("cp.async.wait_group %0;\n" :: "n"(N));
}

// ---------------------------------------------------------------------------
// fp16 GEMM: D[M,N] = A@B^T, A single fp16, B = Bh (+ Bl if TERMS==2).
// BK=32 2-stage cp.async, ldmatrix fragments, STR=40 ushorts (conflict-free).
// EPI: 0 = fp32 + bias (CWB)
//      1 = fp16 out: acc + addvec[row % B][col]  (ZW build, CWB fold)
//      2 = fp16 out + bias (+relu if ACT)    (label MLP L2/L3, P1, P2)
//      3 = fp32 + bias, [T,B]->[B,T] perm    (P3)
// ---------------------------------------------------------------------------
template<int BM, int BN, int WM, int WN, int EPI, int ACT, int TERMS>
__global__ void __launch_bounds__((BM / WM) * (BN / WN) * 32, 2)
hgemm(const unsigned short* __restrict__ A,
      const unsigned short* __restrict__ Bh, const unsigned short* __restrict__ Bl,
      const float* __restrict__ bias,
      const float* __restrict__ addvec,
      float* __restrict__ outf,
      unsigned short* __restrict__ outh,
      int M, int N, int K)
{
    constexpr int BK = 32;
    constexpr int STR = BK + 8;              // 40 ushorts
    constexpr int ATI = BM * STR;
    constexpr int BTI = BN * STR;
    constexpr int STAGE = ATI + TERMS * BTI;
    constexpr int WARPS_N = BN / WN;
    constexpr int NTH = (BM / WM) * (BN / WN) * 32;
    constexpr int MI = WM / 16, NI = WN / 8;

    extern __shared__ unsigned short sm[];

    const int tid  = threadIdx.x;
    const int warp = tid >> 5, lane = tid & 31;
    const int g = lane >> 2, t = lane & 3;
    const int wm0 = (warp / WARPS_N) * WM;
    const int wn0 = (warp % WARPS_N) * WN;
    const int m0 = blockIdx.y * BM;
    const int n0 = blockIdx.x * BN;

    const uint32_t smb = (uint32_t)__cvta_generic_to_shared(sm);
    const int aRow = (lane & 7) + ((lane >> 3) & 1) * 8;
    const int aKh  = (lane >> 4) * 16;
    const int bRow = (lane & 7) + (lane >> 4) * 8;
    const int bKh  = ((lane >> 3) & 1) * 16;
    const uint32_t aBase = smb + (uint32_t)(wm0 + aRow) * STR * 2 + aKh;
    const uint32_t bBase = smb + (uint32_t)(ATI + (wn0 + bRow) * STR) * 2 + bKh;

    float acc[MI][NI][4];
#pragma unroll
    for (int mi = 0; mi < MI; mi++)
#pragma unroll
        for (int ni = 0; ni < NI; ni++)
#pragma unroll
            for (int q = 0; q < 4; q++) acc[mi][ni][q] = 0.f;

    auto load_stage = [&](int k0, int s) {
        unsigned short* st = sm + s * STAGE;
#pragma unroll
        for (int i = tid; i < BM * 4; i += NTH) {
            int r = i >> 2, c = i & 3;
            cp_async16(st + r * STR + c * 8, A + (size_t)(m0 + r) * K + k0 + c * 8);
        }
#pragma unroll
        for (int i = tid; i < BN * 4; i += NTH) {
            int r = i >> 2, c = i & 3;
            const size_t gs = (size_t)(n0 + r) * K + k0 + c * 8;
            cp_async16(st + ATI + r * STR + c * 8, Bh + gs);
            if (TERMS == 2)
                cp_async16(st + ATI + BTI + r * STR + c * 8, Bl + gs);
        }
        cp_commit();
    };

    const int KT = K / BK;
    load_stage(0, 0);

    for (int kt = 0; kt < KT; kt++) {
        const int s = kt & 1;
        if (kt + 1 < KT) { load_stage((kt + 1) * BK, s ^ 1); cp_wait<1>(); }
        else             { cp_wait<0>(); }
        __syncthreads();

        const uint32_t stOff = (uint32_t)(s * STAGE) * 2;
        const uint32_t aA = aBase + stOff;
        const uint32_t bH = bBase + stOff;
        const uint32_t bL = bH + (uint32_t)BTI * 2;

#pragma unroll
        for (int kk = 0; kk < BK; kk += 16) {
            unsigned ah[MI][4], bh[NI][2], bl[NI][2];
#pragma unroll
            for (int mi = 0; mi < MI; mi++)
                ldsm4(ah[mi][0], ah[mi][1], ah[mi][2], ah[mi][3],
                      aA + (uint32_t)(mi * 16 * STR + kk) * 2);
#pragma unroll
            for (int p = 0; p < NI / 2; p++) {
                ldsm4(bh[2*p][0], bh[2*p][1], bh[2*p+1][0], bh[2*p+1][1],
                      bH + (uint32_t)(p * 16 * STR + kk) * 2);
                if (TERMS == 2)
                    ldsm4(bl[2*p][0], bl[2*p][1], bl[2*p+1][0], bl[2*p+1][1],
                          bL + (uint32_t)(p * 16 * STR + kk) * 2);
            }
#pragma unroll
            for (int mi = 0; mi < MI; mi++)
#pragma unroll
                for (int ni = 0; ni < NI; ni++) {
                    mma16816(acc[mi][ni][0], acc[mi][ni][1], acc[mi][ni][2], acc[mi][ni][3],
                             ah[mi][0], ah[mi][1], ah[mi][2], ah[mi][3], bh[ni][0], bh[ni][1]);
                    if (TERMS == 2)
                        mma16816(acc[mi][ni][0], acc[mi][ni][1], acc[mi][ni][2], acc[mi][ni][3],
                                 ah[mi][0], ah[mi][1], ah[mi][2], ah[mi][3], bl[ni][0], bl[ni][1]);
                }
        }
        __syncthreads();
    }

    // ---- Epilogues ----
    if (EPI == 0 || EPI == 2 || EPI == 3) {
        float2 bv[NI];
#pragma unroll
        for (int ni = 0; ni < NI; ni++)
            bv[ni] = *(const float2*)(bias + n0 + wn0 + ni * 8 + 2 * t);

#pragma unroll
        for (int mi = 0; mi < MI; mi++) {
            int row0 = m0 + wm0 + mi * 16 + g;
#pragma unroll
            for (int ni = 0; ni < NI; ni++) {
                int col = n0 + wn0 + ni * 8 + 2 * t;
                float v0 = acc[mi][ni][0] + bv[ni].x;
                float v1 = acc[mi][ni][1] + bv[ni].y;
                float v2 = acc[mi][ni][2] + bv[ni].x;
                float v3 = acc[mi][ni][3] + bv[ni].y;
                if (ACT == 1) {
                    v0 = fmaxf(v0, 0.f); v1 = fmaxf(v1, 0.f);
                    v2 = fmaxf(v2, 0.f); v3 = fmaxf(v3, 0.f);
                }
                if (EPI == 0) {
                    *(float2*)(outf + (size_t)row0 * N + col)       = make_float2(v0, v1);
                    *(float2*)(outf + (size_t)(row0 + 8) * N + col) = make_float2(v2, v3);
                } else if (EPI == 2) {
                    *(ushort2*)(outh + (size_t)row0 * N + col) =
                        make_ushort2(h_of(v0), h_of(v1));
                    *(ushort2*)(outh + (size_t)(row0 + 8) * N + col) =
                        make_ushort2(h_of(v2), h_of(v3));
                } else {
                    int tt0 = row0 / B_DIM, bb0 = row0 % B_DIM;
                    int r1 = row0 + 8;
                    int tt1 = r1 / B_DIM, bb1 = r1 % B_DIM;
                    *(float2*)(outf + ((size_t)bb0 * T_DIM + tt0) * D_DIM + col) = make_float2(v0, v1);
                    *(float2*)(outf + ((size_t)bb1 * T_DIM + tt1) * D_DIM + col) = make_float2(v2, v3);
                }
            }
        }
    } else {
        // EPI == 1: fp16 out, + addvec (CWB incl. biases)
#pragma unroll
        for (int mi = 0; mi < MI; mi++) {
            int row0 = m0 + wm0 + mi * 16 + g;
#pragma unroll
            for (int ni = 0; ni < NI; ni++) {
                int col = n0 + wn0 + ni * 8 + 2 * t;
                float2 a0 = *(const float2*)(addvec + (size_t)(row0 & (B_DIM - 1)) * N + col);
                float2 a1 = *(const float2*)(addvec + (size_t)((row0 + 8) & (B_DIM - 1)) * N + col);
                *(ushort2*)(outh + (size_t)row0 * N + col) =
                    make_ushort2(h_of(acc[mi][ni][0] + a0.x), h_of(acc[mi][ni][1] + a0.y));
                *(ushort2*)(outh + (size_t)(row0 + 8) * N + col) =
                    make_ushort2(h_of(acc[mi][ni][2] + a1.x), h_of(acc[mi][ni][3] + a1.y));
            }
        }
    }
}

// ---------------------------------------------------------------------------
// Persistent LSTM recurrence: 256 CTAs (2/SM), tile 64x128, BK=64, Whh 1-term,
// ZW[t] register prefetch, per-m-group barriers, fast MUFU activations.
// ---------------------------------------------------------------------------
__global__ void __launch_bounds__(256, 2)
lstm_persistent(const unsigned short* __restrict__ Whh_h,
                const unsigned short* __restrict__ ZW,   // fp16 [T][B][G] (perm)
                unsigned short* __restrict__ H_h)
{
    constexpr int BM = 64, BN = 128, BK = 64, WM = 32, WN = 32;
    constexpr int STR = BK + 8;                // 72 ushorts
    constexpr int ATI = BM * STR, BTI = BN * STR;
    constexpr int STAGE = ATI + BTI;
    constexpr int WARPS_N = BN / WN;
    constexpr int NTH = 256;
    constexpr int MI = WM / 16, NI = WN / 8;   // 2, 4
    constexpr int K = H_DIM, N = G_DIM;
    constexpr int KT = K / BK;                 // 8

    extern __shared__ unsigned short sm[];

    const int tid  = threadIdx.x;
    const int warp = tid >> 5, lane = tid & 31;
    const int g = lane >> 2, t4 = lane & 3;
    const int wm0 = (warp / WARPS_N) * WM;
    const int wn0 = (warp % WARPS_N) * WN;
    const int bid = blockIdx.x;
    const int mg = bid >> 4;              // m-group (0..15)
    const int m0 = mg * BM;
    const int n0 = (bid & 15) * BN;

    const uint32_t smb = (uint32_t)__cvta_generic_to_shared(sm);
    const int aRow = (lane & 7) + ((lane >> 3) & 1) * 8;
    const int aKh  = (lane >> 4) * 16;
    const int bRow = (lane & 7) + (lane >> 4) * 8;
    const int bKh  = ((lane >> 3) & 1) * 16;
    const uint32_t aBase = smb + (uint32_t)(wm0 + aRow) * STR * 2 + aKh;
    const uint32_t bBase = smb + (uint32_t)(ATI + (wn0 + bRow) * STR) * 2 + bKh;

    const bool hi_half = (t4 & 1);

    // Per-thread (row, zw-offset) for the cell lanes (fixed across steps)
    int rowIdx[MI];
    size_t zwOff[MI][NI];
#pragma unroll
    for (int mi = 0; mi < MI; mi++) {
        int row0 = m0 + wm0 + mi * 16 + g;
        int row = hi_half ? row0 + 8 : row0;
        rowIdx[mi] = row;
#pragma unroll
        for (int ni = 0; ni < NI; ni++) {
            int col = n0 + wn0 + ni * 8 + 2 * t4;
            zwOff[mi][ni] = (size_t)row * G_DIM + (col & ~3);
        }
    }

    float creg[MI][NI];
#pragma unroll
    for (int mi = 0; mi < MI; mi++)
#pragma unroll
        for (int ni = 0; ni < NI; ni++) creg[mi][ni] = 0.f;

    for (int t = 0; t < T_DIM; t++) {
        // ---- Prefetch ZW[t] into registers (overlaps with MMA below) ----
        const unsigned short* zwb = ZW + (size_t)t * B_DIM * G_DIM;
        ushort4 zpre[MI][NI];
#pragma unroll
        for (int mi = 0; mi < MI; mi++)
#pragma unroll
            for (int ni = 0; ni < NI; ni++)
                zpre[mi][ni] = *(const ushort4*)(zwb + zwOff[mi][ni]);

        float acc[MI][NI][4];
#pragma unroll
        for (int mi = 0; mi < MI; mi++)
#pragma unroll
            for (int ni = 0; ni < NI; ni++)
#pragma unroll
                for (int q = 0; q < 4; q++) acc[mi][ni][q] = 0.f;

        if (t > 0) {
            const unsigned short* Ah = H_h + (size_t)(t - 1) * B_DIM * H_DIM;

            auto load_stage = [&](int k0, int s) {
                unsigned short* st = sm + s * STAGE;
#pragma unroll
                for (int i = tid; i < BM * 8; i += NTH) {
                    int r = i >> 3, c = i & 7;
                    cp_async16(st + r * STR + c * 8, Ah + (size_t)(m0 + r) * K + k0 + c * 8);
                }
#pragma unroll
                for (int i = tid; i < BN * 8; i += NTH) {
                    int r = i >> 3, c = i & 7;
                    cp_async16(st + ATI + r * STR + c * 8,
                               Whh_h + (size_t)(n0 + r) * K + k0 + c * 8);
                }
                cp_commit();
            };

            load_stage(0, 0);
            for (int kt = 0; kt < KT; kt++) {
                const int s = kt & 1;
                if (kt + 1 < KT) { load_stage((kt + 1) * BK, s ^ 1); cp_wait<1>(); }
                else             { cp_wait<0>(); }
                __syncthreads();

                const uint32_t stOff = (uint32_t)(s * STAGE) * 2;
                const uint32_t aA = aBase + stOff;
                const uint32_t bH = bBase + stOff;

#pragma unroll
                for (int kk = 0; kk < BK; kk += 16) {
                    unsigned ah[MI][4], bh[NI][2];
#pragma unroll
                    for (int mi = 0; mi < MI; mi++)
                        ldsm4(ah[mi][0], ah[mi][1], ah[mi][2], ah[mi][3],
                              aA + (uint32_t)(mi * 16 * STR + kk) * 2);
#pragma unroll
                    for (int p = 0; p < NI / 2; p++)
                        ldsm4(bh[2*p][0], bh[2*p][1], bh[2*p+1][0], bh[2*p+1][1],
                              bH + (uint32_t)(p * 16 * STR + kk) * 2);
#pragma unroll
                    for (int mi = 0; mi < MI; mi++)
#pragma unroll
                        for (int ni = 0; ni < NI; ni++)
                            mma16816(acc[mi][ni][0], acc[mi][ni][1], acc[mi][ni][2], acc[mi][ni][3],
                                     ah[mi][0], ah[mi][1], ah[mi][2], ah[mi][3], bh[ni][0], bh[ni][1]);
                }
                __syncthreads();
            }
        }

        // ---- Cell epilogue (c in registers; ZW prefetched; MUFU activations) ----
        unsigned short* hh = H_h + (size_t)t * B_DIM * H_DIM;
#pragma unroll
        for (int mi = 0; mi < MI; mi++) {
            int row = rowIdx[mi];
#pragma unroll
            for (int ni = 0; ni < NI; ni++) {
                int col = n0 + wn0 + ni * 8 + 2 * t4;
                float c0 = acc[mi][ni][0], c1 = acc[mi][ni][1];
                float c2 = acc[mi][ni][2], c3 = acc[mi][ni][3];
                float sx = __shfl_xor_sync(0xffffffffu, hi_half ? c0 : c2, 1);
                float sy = __shfl_xor_sync(0xffffffffu, hi_half ? c1 : c3, 1);
                float gi, gf, gg, go;
                if (!hi_half) { gi = c0; gf = c1; gg = sx; go = sy; }
                else          { gi = sx; gf = sy; gg = c2; go = c3; }

                ushort4 zr = zpre[mi][ni];
                gi += f_of(zr.x); gf += f_of(zr.y);
                gg += f_of(zr.z); go += f_of(zr.w);

                float ig = fsigmoid(gi);
                float fg = fsigmoid(gf);
                float gt = ftanh(gg);
                float og = fsigmoid(go);

                float cn = fg * creg[mi][ni] + ig * gt;
                creg[mi][ni] = cn;
                hh[(size_t)row * H_DIM + (col >> 2)] = h_of(og * ftanh(cn));
            }
        }

        // ---- Per-m-group barrier: 16 arrivals, independent per group ----
        if (t < T_DIM - 1) {
            __syncthreads();
            if (tid == 0) {
                __threadfence();
                unsigned* ctr = &g_bar_ctrs[mg * 32];
                atomicAdd(ctr, 1u);
                unsigned target = (unsigned)(t + 1) * NGROUP;
                volatile unsigned* vctr = ctr;
                while (*vctr < target) { }
                __threadfence();
            }
            __syncthreads();
        }
    }

    // Deterministic counter reset for graph replay
    __syncthreads();
    if (tid == 0) {
        unsigned d = atomicAdd(&g_done_ctr, 1u);
        if (d == GRID_P - 1) {
#pragma unroll
            for (int q = 0; q < 16; q++) g_bar_ctrs[q * 32] = 0;
            g_done_ctr = 0;
            __threadfence();
        }
    }
}

// ---------------------------------------------------------------------------
// f32x2 SGEMM (label MLP layer 1, K=16). OUT: 0 fp32, 1 single fp16.
// ---------------------------------------------------------------------------
__device__ __forceinline__ void ffma2(unsigned long long& d,
                                      unsigned long long a,
                                      unsigned long long b) {
    asm("fma.rn.f32x2 %0, %1, %2, %0;" : "+l"(d) : "l"(a), "l"(b));
}
__device__ __forceinline__ unsigned long long pack2(float lo, float hi) {
    unsigned long long r;
    asm("mov.b64 %0, {%1, %2};" : "=l"(r) : "f"(lo), "f"(hi));
    return r;
}
__device__ __forceinline__ float2 unpack2(unsigned long long u) {
    float2 f;
    asm("mov.b64 {%0, %1}, %2;" : "=f"(f.x), "=f"(f.y) : "l"(u));
    return f;
}

template<int BM, int BN, int BK, int TM, int TN, int ACT, int OUT>
__global__ void gemm2_kernel(const float* __restrict__ A,
                             const float* __restrict__ W,
                             const float* __restrict__ bias,
                             float* __restrict__ C,
                             unsigned short* __restrict__ uh,
                             int M, int N, int K)
{
    constexpr int AS_STRIDE = BM + 4;
    constexpr int WS_STRIDE = BN + 4;
    __shared__ float As[BK][AS_STRIDE];
    __shared__ float Ws[BK][WS_STRIDE];

    constexpr int NTH = (BM / TM) * (BN / TN);
    const int tid = threadIdx.x;
    const int tx = tid % (BN / TN);
    const int ty = tid / (BN / TN);
    const int m0 = blockIdx.y * BM;
    const int n0 = blockIdx.x * BN;

    unsigned long long acc2[TM / 2][TN];
#pragma unroll
    for (int p = 0; p < TM / 2; p++)
#pragma unroll
        for (int j = 0; j < TN; j++) acc2[p][j] = 0ULL;

    for (int k0 = 0; k0 < K; k0 += BK) {
#pragma unroll
        for (int i = tid * 4; i < BM * BK; i += NTH * 4) {
            int m = i / BK, k = i % BK;
            float4 v = *(const float4*)(A + (long)(m0 + m) * K + (k0 + k));
            As[k + 0][m] = v.x; As[k + 1][m] = v.y;
            As[k + 2][m] = v.z; As[k + 3][m] = v.w;
        }
#pragma unroll
        for (int i = tid * 4; i < BN * BK; i += NTH * 4) {
            int n = i / BK, k = i % BK;
            float4 v = *(const float4*)(W + (long)(n0 + n) * K + (k0 + k));
            Ws[k + 0][n] = v.x; Ws[k + 1][n] = v.y;
            Ws[k + 2][n] = v.z; Ws[k + 3][n] = v.w;
        }
        __syncthreads();

#pragma unroll
        for (int k = 0; k < BK; k++) {
            unsigned long long am2[TM / 2];
            const ulonglong2* ap = reinterpret_cast<const ulonglong2*>(&As[k][ty * TM]);
#pragma unroll
            for (int q = 0; q < TM / 4; q++) {
                ulonglong2 tt = ap[q];
                am2[2 * q + 0] = tt.x;
                am2[2 * q + 1] = tt.y;
            }
            float4 w4 = *reinterpret_cast<const float4*>(&Ws[k][tx * TN]);
            unsigned long long wd[TN];
            wd[0] = pack2(w4.x, w4.x); wd[1] = pack2(w4.y, w4.y);
            wd[2] = pack2(w4.z, w4.z); wd[3] = pack2(w4.w, w4.w);
#pragma unroll
            for (int p = 0; p < TM / 2; p++)
#pragma unroll
                for (int j = 0; j < TN; j++) ffma2(acc2[p][j], am2[p], wd[j]);
        }
        __syncthreads();
    }

    float4 bv = make_float4(0.f, 0.f, 0.f, 0.f);
    if (bias) bv = *reinterpret_cast<const float4*>(bias + n0 + tx * TN);

#pragma unroll
    for (int p = 0; p < TM / 2; p++) {
        float2 v0 = unpack2(acc2[p][0]);
        float2 v1 = unpack2(acc2[p][1]);
        float2 v2 = unpack2(acc2[p][2]);
        float2 v3 = unpack2(acc2[p][3]);
        float4 rowA = make_float4(v0.x + bv.x, v1.x + bv.y, v2.x + bv.z, v3.x + bv.w);
        float4 rowB = make_float4(v0.y + bv.x, v1.y + bv.y, v2.y + bv.z, v3.y + bv.w);
        if (ACT == 1) {
            rowA.x = fmaxf(rowA.x, 0.f); rowA.y = fmaxf(rowA.y, 0.f);
            rowA.z = fmaxf(rowA.z, 0.f); rowA.w = fmaxf(rowA.w, 0.f);
            rowB.x = fmaxf(rowB.x, 0.f); rowB.y = fmaxf(rowB.y, 0.f);
            rowB.z = fmaxf(rowB.z, 0.f); rowB.w = fmaxf(rowB.w, 0.f);
        }
        int mA = m0 + ty * TM + 2 * p;
        int n  = n0 + tx * TN;
        if (OUT == 0) {
            *reinterpret_cast<float4*>(C + (long)mA * N + n) = rowA;
            *reinterpret_cast<float4*>(C + (long)(mA + 1) * N + n) = rowB;
        } else {
            *(ushort4*)(uh + (size_t)mA * N + n) =
                make_ushort4(h_of(rowA.x), h_of(rowA.y), h_of(rowA.z), h_of(rowA.w));
            *(ushort4*)(uh + (size_t)(mA + 1) * N + n) =
                make_ushort4(h_of(rowB.x), h_of(rowB.y), h_of(rowB.z), h_of(rowB.w));
        }
    }
}

// ---------------------------------------------------------------------------
// Prep kernels
// ---------------------------------------------------------------------------
__device__ __forceinline__ void split4w(const float4* src, int i,
                                        ushort4* hi, ushort4* lo) {
    float4 v = src[i];
    ushort4 h, l;
    hsplit(v.x, h.x, l.x); hsplit(v.y, h.y, l.y);
    hsplit(v.z, h.z, l.z); hsplit(v.w, h.w, l.w);
    hi[i] = h;
    if (lo) lo[i] = l;
}

__device__ __forceinline__ void permsplit4w(const float* src, int i,
                                            ushort4* hi, ushort4* lo) {
    int r = i / (H_DIM / 4);
    int c = i % (H_DIM / 4);
    int j = r >> 2, gg = r & 3;
    float4 v = ((const float4*)src)[(size_t)(gg * H_DIM + j) * (H_DIM / 4) + c];
    ushort4 h, l;
    hsplit(v.x, h.x, l.x); hsplit(v.y, h.y, l.y);
    hsplit(v.z, h.z, l.z); hsplit(v.w, h.w, l.w);
    size_t o = (size_t)r * (H_DIM / 4) + c;
    hi[o] = h;
    if (lo) lo[o] = l;
}

__global__ void prep_weights(const float* __restrict__ P1, const float* __restrict__ P2,
                             const float* __restrict__ P3,
                             const float* __restrict__ Wih, const float* __restrict__ Whh,
                             const float* __restrict__ W2, const float* __restrict__ W3,
                             const float* __restrict__ bih, const float* __restrict__ bhh,
                             ushort4* P1h, ushort4* P2h,
                             ushort4* P3h, ushort4* P3l,
                             ushort4* Wihh, ushort4* Wihl, ushort4* Whhh,
                             ushort4* W2h, ushort4* W2l, ushort4* W3h, ushort4* W3l,
                             float* bp, float* zb)
{
    const int S0 = H_DIM * H_DIM / 4;              // P1
    const int S1 = S0 + H_DIM * H_DIM / 4;         // P2
    const int S2 = S1 + D_DIM * H_DIM / 4;         // P3
    const int S3 = S2 + G_DIM * H_DIM / 4;         // Wih
    const int S4 = S3 + G_DIM * H_DIM / 4;         // Whh
    const int S5 = S4 + H_DIM * H_DIM / 4;         // W2
    const int S6 = S5 + H_DIM * H_DIM / 4;         // W3
    int i = blockIdx.x * blockDim.x + threadIdx.x;
    if      (i < S0) split4w((const float4*)P1, i, P1h, nullptr);
    else if (i < S1) split4w((const float4*)P2, i - S0, P2h, nullptr);
    else if (i < S2) split4w((const float4*)P3, i - S1, P3h, P3l);
    else if (i < S3) permsplit4w(Wih, i - S2, Wihh, Wihl);
    else if (i < S4) permsplit4w(Whh, i - S3, Whhh, nullptr);
    else if (i < S5) split4w((const float4*)W2, i - S4, W2h, W2l);
    else if (i < S6) split4w((const float4*)W3, i - S5, W3h, W3l);
    else if (i < S6 + G_DIM) {
        int k = i - S6;
        int j = k >> 2, gg = k & 3;
        bp[k] = bih[gg * H_DIM + j] + bhh[gg * H_DIM + j];
    }
    else if (i < S6 + G_DIM + H_DIM) {
        zb[i - S6 - G_DIM] = 0.f;
    }
}

// z -> single fp16
__global__ void cvt_half_kernel(const float4* __restrict__ src,
                                ushort4* __restrict__ dst, int n4)
{
    int i = blockIdx.x * blockDim.x + threadIdx.x;
    if (i >= n4) return;
    float4 v = src[i];
    dst[i] = make_ushort4(h_of(v.x), h_of(v.y), h_of(v.z), h_of(v.w));
}

// ---------------------------------------------------------------------------
// Launch
// ---------------------------------------------------------------------------
extern "C" void kernel_launch(void* const* d_in, const int* in_sizes, int n_in,
                              void* d_out, int out_size)
{
    const float* labels = (const float*)d_in[0];
    const float* z      = (const float*)d_in[1];
    const float* W1     = (const float*)d_in[2];
    const float* b1     = (const float*)d_in[3];
    const float* W2     = (const float*)d_in[4];
    const float* b2     = (const float*)d_in[5];
    const float* W3     = (const float*)d_in[6];
    const float* Wih    = (const float*)d_in[7];
    const float* Whh    = (const float*)d_in[8];
    const float* bih    = (const float*)d_in[9];
    const float* bhh    = (const float*)d_in[10];
    const float* P1     = (const float*)d_in[11];
    const float* pb1    = (const float*)d_in[12];
    const float* P2     = (const float*)d_in[13];
    const float* pb2    = (const float*)d_in[14];
    const float* P3     = (const float*)d_in[15];
    const float* pb3    = (const float*)d_in[16];
    float* out = (float*)d_out;

    float *bperm, *zbias, *CWB;
    unsigned short *x1h, *x2h, *conds_h;
    unsigned short *W2_h, *W2_l, *W3_h, *W3_l;
    unsigned short *Wih_h, *Wih_l, *Whh_h;
    unsigned short *P1_h, *P2_h, *P3_h, *P3_l;
    unsigned short *z_h, *ZW, *H_h, *y1_h, *y2_h;
    cudaGetSymbolAddress((void**)&bperm,  g_bperm);
    cudaGetSymbolAddress((void**)&zbias,  g_zbias);
    cudaGetSymbolAddress((void**)&x1h,    g_x1h);
    cudaGetSymbolAddress((void**)&x2h,    g_x2h);
    cudaGetSymbolAddress((void**)&conds_h, g_conds_h);
    cudaGetSymbolAddress((void**)&W2_h,   g_W2_h);
    cudaGetSymbolAddress((void**)&W2_l,   g_W2_l);
    cudaGetSymbolAddress((void**)&W3_h,   g_W3_h);
    cudaGetSymbolAddress((void**)&W3_l,   g_W3_l);
    cudaGetSymbolAddress((void**)&Wih_h,  g_Wih_h);
    cudaGetSymbolAddress((void**)&Wih_l,  g_Wih_l);
    cudaGetSymbolAddress((void**)&Whh_h,  g_Whh_h);
    cudaGetSymbolAddress((void**)&P1_h,   g_P1_h);
    cudaGetSymbolAddress((void**)&P2_h,   g_P2_h);
    cudaGetSymbolAddress((void**)&P3_h,   g_P3_h);
    cudaGetSymbolAddress((void**)&P3_l,   g_P3_l);
    cudaGetSymbolAddress((void**)&CWB,    g_CWB);
    cudaGetSymbolAddress((void**)&z_h,    g_z_h);
    cudaGetSymbolAddress((void**)&ZW,     g_ZW);
    cudaGetSymbolAddress((void**)&H_h,    g_H_h);
    cudaGetSymbolAddress((void**)&y1_h,   g_y1_h);
    cudaGetSymbolAddress((void**)&y2_h,   g_y2_h);

    const int TB = TB_DIM;

    // Dynamic smem: hgemm BK=32 (STR=40); persistent BK=64 (STR=72)
    constexpr int SM128_T2 = 2 * (128 * 40 + 2 * 128 * 40) * 2;  // 61440 B
    constexpr int SM128_T1 = 2 * (128 * 40 + 1 * 128 * 40) * 2;  // 40960 B
    constexpr int SM64_T2  = 2 * (64 * 40 + 2 * 64 * 40) * 2;    // 30720 B (64x64)
    constexpr int SM64B    = 2 * (128 * 40 + 2 * 64 * 40) * 2;   // 40960 B (BN=64)
    constexpr int SMP      = 2 * (64 * 72 + 128 * 72) * 2;       // 55296 B
    cudaFuncSetAttribute((const void*)hgemm<128,128,64,32,0,0,2>,
                         cudaFuncAttributeMaxDynamicSharedMemorySize, SM128_T2);
    cudaFuncSetAttribute((const void*)hgemm<128,128,64,32,1,0,1>,
                         cudaFuncAttributeMaxDynamicSharedMemorySize, SM128_T1);
    cudaFuncSetAttribute((const void*)hgemm<128,128,64,32,2,1,1>,
                         cudaFuncAttributeMaxDynamicSharedMemorySize, SM128_T1);
    cudaFuncSetAttribute((const void*)hgemm<64,64,32,32,2,1,2>,
                         cudaFuncAttributeMaxDynamicSharedMemorySize, SM64_T2);
    cudaFuncSetAttribute((const void*)hgemm<64,64,32,32,2,0,2>,
                         cudaFuncAttributeMaxDynamicSharedMemorySize, SM64_T2);
    cudaFuncSetAttribute((const void*)hgemm<128,64,64,16,3,0,2>,
                         cudaFuncAttributeMaxDynamicSharedMemorySize, SM64B);
    cudaFuncSetAttribute((const void*)lstm_persistent,
                         cudaFuncAttributeMaxDynamicSharedMemorySize, SMP);

    // [0] fused weight prep
    {
        const int total = 4 * (H_DIM * H_DIM / 4) + D_DIM * H_DIM / 4
                        + 2 * (G_DIM * H_DIM / 4) + G_DIM + H_DIM;
        prep_weights<<<(total + 255) / 256, 256>>>(
            P1, P2, P3, Wih, Whh, W2, W3, bih, bhh,
            (ushort4*)P1_h, (ushort4*)P2_h,
            (ushort4*)P3_h, (ushort4*)P3_l,
            (ushort4*)Wih_h, (ushort4*)Wih_l, (ushort4*)Whh_h,
            (ushort4*)W2_h, (ushort4*)W2_l, (ushort4*)W3_h, (ushort4*)W3_l,
            bperm, zbias);
    }
    // [1] z -> fp16
    cvt_half_kernel<<<(int)(((size_t)TB * H_DIM / 4) / 256), 256>>>(
        (const float4*)z, (ushort4*)z_h, TB * (H_DIM / 4));

    // [2] Label MLP layer 1 (K=16, f32x2) -> fp16
    gemm2_kernel<64,64,16,4,4,1,1><<<dim3(H_DIM/64, B_DIM/64), 256>>>(
        labels, W1, b1, nullptr, x1h, B_DIM, H_DIM, L_DIM);
    // [3,4] Label MLP layers 2-3 on tensor cores (64x64 tiles, 128 CTAs)
    hgemm<64,64,32,32,2,1,2><<<dim3(H_DIM/64, B_DIM/64), 128, SM64_T2>>>(
        x1h, W2_h, W2_l, b2, nullptr, nullptr, x2h, B_DIM, H_DIM, H_DIM);
    hgemm<64,64,32,32,2,0,2><<<dim3(H_DIM/64, B_DIM/64), 128, SM64_T2>>>(
        x2h, W3_h, W3_l, zbias, nullptr, nullptr, conds_h, B_DIM, H_DIM, H_DIM);

    // [5] CWB = conds @ Wih_perm^T + (bih+bhh)_perm   (2-term, fp32 out)
    hgemm<128,128,64,32,0,0,2><<<dim3(G_DIM/128, B_DIM/128), 256, SM128_T2>>>(
        conds_h, Wih_h, Wih_l, bperm, nullptr,
        CWB, nullptr, B_DIM, G_DIM, H_DIM);
    // [6] ZW = z @ Wih_perm^T + CWB[row % B]   (1-term, fp16 out)
    hgemm<128,128,64,32,1,0,1><<<dim3(G_DIM/128, TB/128), 256, SM128_T1>>>(
        z_h, Wih_h, nullptr, nullptr, CWB,
        nullptr, ZW, TB, G_DIM, H_DIM);

    // [7] Persistent recurrence (per-m-group barriers, fast activations)
    lstm_persistent<<<GRID_P, 256, SMP>>>(Whh_h, ZW, H_h);

    // [8..10] Projection MLP over all T*B rows (P1/P2 1-term, P3 2-term)
    hgemm<128,128,64,32,2,1,1><<<dim3(H_DIM/128, TB/128), 256, SM128_T1>>>(
        H_h, P1_h, nullptr, pb1, nullptr,
        nullptr, y1_h, TB, H_DIM, H_DIM);
    hgemm<128,128,64,32,2,1,1><<<dim3(H_DIM/128, TB/128), 256, SM128_T1>>>(
        y1_h, P2_h, nullptr, pb2, nullptr,
        nullptr, y2_h, TB, H_DIM, H_DIM);
    hgemm<128,64,64,16,3,0,2><<<dim3(D_DIM/64, TB/128), 256, SM64B>>>(
        y2_h, P3_h, P3_l, pb3, nullptr,
        out, nullptr, TB, D_DIM, H_DIM);
}